// round 2
// baseline (speedup 1.0000x reference)
#include <cuda_runtime.h>
#include <cstdint>

#define N_NODES 50000
#define N_EDGES 625000
#define F 128          // F_IN == F_OUT == 128

// ---------------------------------------------------------------------------
// Scratch (__device__ globals => allocation-free)
// ---------------------------------------------------------------------------
__device__ float g_support[(size_t)N_NODES * F];   // x @ W       (25.6 MB)
__device__ int   g_count[N_NODES];                 // histogram / cursor
__device__ int   g_start[N_NODES + 1];             // CSR row starts
__device__ int   g_ecol[N_EDGES];                  // sorted edge cols
__device__ float g_eval[N_EDGES];                  // sorted edge vals

// ---------------------------------------------------------------------------
// Sort pipeline (counting sort of edges by destination row)
// ---------------------------------------------------------------------------
__global__ void zero_count_kernel() {
    int i = blockIdx.x * blockDim.x + threadIdx.x;
    if (i < N_NODES) g_count[i] = 0;
}

__global__ void hist_kernel(const int* __restrict__ rows) {
    int e = blockIdx.x * blockDim.x + threadIdx.x;
    if (e < N_EDGES) atomicAdd(&g_count[rows[e]], 1);
}

// Single-block exclusive scan over 50k counts; also zeros g_count for reuse
// as the scatter cursor. 1024 threads x 49 elements each (50176 >= 50000).
__global__ __launch_bounds__(1024) void scan_kernel() {
    const int CHUNK = 49;
    __shared__ int sums[1024];
    const int t   = threadIdx.x;
    const int beg = t * CHUNK;

    int s = 0;
    #pragma unroll
    for (int i = 0; i < CHUNK; i++) {
        int idx = beg + i;
        if (idx < N_NODES) s += g_count[idx];
    }
    sums[t] = s;
    __syncthreads();

    // Hillis-Steele inclusive scan over 1024 partials
    for (int off = 1; off < 1024; off <<= 1) {
        int v = 0;
        if (t >= off) v = sums[t - off];
        __syncthreads();
        sums[t] += v;
        __syncthreads();
    }
    int run = sums[t] - s;   // exclusive base for this thread's chunk

    #pragma unroll
    for (int i = 0; i < CHUNK; i++) {
        int idx = beg + i;
        if (idx < N_NODES) {
            int v = g_count[idx];
            g_start[idx] = run;
            run += v;
            g_count[idx] = 0;          // reset cursor for scatter
        }
    }
    if (t == 1023) g_start[N_NODES] = run;   // == N_EDGES
}

__global__ void scatter_kernel(const int*   __restrict__ rows,
                               const int*   __restrict__ cols,
                               const float* __restrict__ vals) {
    int e = blockIdx.x * blockDim.x + threadIdx.x;
    if (e >= N_EDGES) return;
    int r = rows[e];
    int p = g_start[r] + atomicAdd(&g_count[r], 1);
    g_ecol[p] = cols[e];
    g_eval[p] = vals[e];
}

// ---------------------------------------------------------------------------
// GEMM: support = x @ W   (32-row x 128-col tile, 256 threads, FFMA-bound)
// ---------------------------------------------------------------------------
__global__ __launch_bounds__(256) void gemm_kernel(const float* __restrict__ x,
                                                   const float* __restrict__ w) {
    __shared__ float xs[32][F];                          // 16 KB
    const int m0 = blockIdx.x * 32;
    const int t  = threadIdx.x;

    {
        float4* xdst = (float4*)&xs[0][0];
        const int nvec = 32 * F / 4;                     // 1024
        #pragma unroll
        for (int i = t; i < nvec; i += 256) {
            int row = i >> 5;
            if (m0 + row < N_NODES)
                xdst[i] = ((const float4*)(x + (size_t)m0 * F))[i];
            else
                xdst[i] = make_float4(0.f, 0.f, 0.f, 0.f);
        }
    }
    __syncthreads();

    const int q = t & 31;                                // col quad
    const int g = t >> 5;                                // row group

    float acc[4][4];
    #pragma unroll
    for (int i = 0; i < 4; i++)
        #pragma unroll
        for (int j = 0; j < 4; j++) acc[i][j] = 0.f;

    const float4* __restrict__ w4 = (const float4*)w;

    #pragma unroll 2
    for (int k = 0; k < F; k += 4) {
        float xr[4][4];
        #pragma unroll
        for (int i = 0; i < 4; i++) {
            float4 xv = *(const float4*)&xs[g * 4 + i][k];
            xr[i][0] = xv.x; xr[i][1] = xv.y; xr[i][2] = xv.z; xr[i][3] = xv.w;
        }
        #pragma unroll
        for (int kk = 0; kk < 4; kk++) {
            float4 wv = w4[(size_t)(k + kk) * 32 + q];
            #pragma unroll
            for (int i = 0; i < 4; i++) {
                acc[i][0] += xr[i][kk] * wv.x;
                acc[i][1] += xr[i][kk] * wv.y;
                acc[i][2] += xr[i][kk] * wv.z;
                acc[i][3] += xr[i][kk] * wv.w;
            }
        }
    }

    #pragma unroll
    for (int i = 0; i < 4; i++) {
        int m = m0 + g * 4 + i;
        if (m < N_NODES) {
            float4 v = make_float4(acc[i][0], acc[i][1], acc[i][2], acc[i][3]);
            *(float4*)&g_support[(size_t)m * F + q * 4] = v;
        }
    }
}

// ---------------------------------------------------------------------------
// CSR SpMM: one warp per output row. Atomic-free; bias fused.
// lane f accumulates out[r][4f..4f+3] over the row's edges.
// ---------------------------------------------------------------------------
__global__ __launch_bounds__(256) void spmm_csr_kernel(const float* __restrict__ bias,
                                                       float*       __restrict__ out) {
    const int warp = (blockIdx.x * blockDim.x + threadIdx.x) >> 5;
    const int lane = threadIdx.x & 31;
    if (warp >= N_NODES) return;
    const int r = warp;

    const int s = g_start[r];
    const int e = g_start[r + 1];

    float4 acc = *(const float4*)&bias[lane * 4];        // warp-uniform L1 hit

    for (int base = s; base < e; base += 32) {
        int   idx = base + lane;
        int   c   = 0;
        float v   = 0.f;
        if (idx < e) { c = g_ecol[idx]; v = g_eval[idx]; }
        const int cnt = min(32, e - base);
        for (int j = 0; j < cnt; j++) {
            int   cj = __shfl_sync(0xffffffffu, c, j);
            float vj = __shfl_sync(0xffffffffu, v, j);
            float4 sup = *(const float4*)&g_support[(size_t)cj * F + lane * 4];
            acc.x += vj * sup.x;
            acc.y += vj * sup.y;
            acc.z += vj * sup.z;
            acc.w += vj * sup.w;
        }
    }

    *(float4*)&out[(size_t)r * F + lane * 4] = acc;
}

// ---------------------------------------------------------------------------
// Launch. Inputs: 0=x, 1=weight, 2=bias, 3=edge_vals, 4=edge_rows, 5=edge_cols
// ---------------------------------------------------------------------------
extern "C" void kernel_launch(void* const* d_in, const int* in_sizes, int n_in,
                              void* d_out, int out_size) {
    const float* x    = (const float*)d_in[0];
    const float* w    = (const float*)d_in[1];
    const float* bias = (const float*)d_in[2];
    const float* vals = (const float*)d_in[3];
    const int*   rows = (const int*)d_in[4];
    const int*   cols = (const int*)d_in[5];
    float*       out  = (float*)d_out;

    // CSR build (counting sort by row)
    zero_count_kernel<<<(N_NODES + 255) / 256, 256>>>();
    hist_kernel<<<(N_EDGES + 255) / 256, 256>>>(rows);
    scan_kernel<<<1, 1024>>>();
    scatter_kernel<<<(N_EDGES + 255) / 256, 256>>>(rows, cols, vals);

    // support = x @ W
    gemm_kernel<<<(N_NODES + 31) / 32, 256>>>(x, w);

    // out = A_csr @ support + bias  (atomic-free)
    {
        const long long threads = (long long)N_NODES * 32;
        spmm_csr_kernel<<<(int)((threads + 255) / 256), 256>>>(bias, out);
    }
}

// round 3
// speedup vs baseline: 1.7076x; 1.7076x over previous
#include <cuda_runtime.h>
#include <cstdint>

#define N_NODES 50000
#define N_EDGES 625000
#define F 128
#define SCAN_BLOCKS 49          // 49 * 1024 = 50176 >= N_NODES

// ---------------------------------------------------------------------------
// Scratch (__device__ globals => allocation-free)
// ---------------------------------------------------------------------------
__device__ float g_support[(size_t)N_NODES * F];   // x @ W  (25.6 MB)
__device__ int   g_count[N_NODES];                 // histogram / scatter cursor
__device__ int   g_start[N_NODES + 1];             // CSR row starts
__device__ int2  g_edge[N_EDGES];                  // packed {col, f32-bits(val)} sorted by row
__device__ int   g_bsum[SCAN_BLOCKS];              // per-block scan totals
__device__ int   g_boff[SCAN_BLOCKS];              // exclusive block offsets

// ---------------------------------------------------------------------------
// CSR build: zero -> hist -> scan(3 kernels) -> scatter
// ---------------------------------------------------------------------------
__global__ void zero_count_kernel() {
    int i = blockIdx.x * blockDim.x + threadIdx.x;
    if (i < N_NODES) g_count[i] = 0;
}

__global__ void hist_kernel(const int* __restrict__ rows) {
    int e = blockIdx.x * blockDim.x + threadIdx.x;
    if (e < N_EDGES) atomicAdd(&g_count[rows[e]], 1);   // no return use -> RED
}

// Phase 1: per-block (1024-wide) exclusive scan, coalesced.
__global__ __launch_bounds__(1024) void scan1_kernel() {
    __shared__ int sm[1024];
    const int t   = threadIdx.x;
    const int idx = blockIdx.x * 1024 + t;
    const int v   = (idx < N_NODES) ? g_count[idx] : 0;
    sm[t] = v;
    __syncthreads();
    #pragma unroll
    for (int off = 1; off < 1024; off <<= 1) {
        int add = (t >= off) ? sm[t - off] : 0;
        __syncthreads();
        if (t >= off) sm[t] += add;
        __syncthreads();
    }
    if (idx < N_NODES) g_start[idx] = sm[t] - v;        // exclusive, local
    if (t == 1023) g_bsum[blockIdx.x] = sm[1023];       // block total
}

// Phase 2: scan the 49 block totals (one tiny block).
__global__ __launch_bounds__(64) void scan2_kernel() {
    __shared__ int sm[64];
    const int t = threadIdx.x;
    const int v = (t < SCAN_BLOCKS) ? g_bsum[t] : 0;
    sm[t] = v;
    __syncthreads();
    #pragma unroll
    for (int off = 1; off < 64; off <<= 1) {
        int add = (t >= off) ? sm[t - off] : 0;
        __syncthreads();
        if (t >= off) sm[t] += add;
        __syncthreads();
    }
    if (t < SCAN_BLOCKS) g_boff[t] = sm[t] - v;         // exclusive
}

// Phase 3: add block offsets, reset cursors, cap sentinel.
__global__ __launch_bounds__(1024) void scan3_kernel() {
    const int idx = blockIdx.x * 1024 + threadIdx.x;
    if (idx < N_NODES) {
        g_start[idx] += g_boff[blockIdx.x];
        g_count[idx] = 0;
    }
    if (idx == 0) g_start[N_NODES] = N_EDGES;
}

__global__ void scatter_kernel(const int*   __restrict__ rows,
                               const int*   __restrict__ cols,
                               const float* __restrict__ vals) {
    int e = blockIdx.x * blockDim.x + threadIdx.x;
    if (e >= N_EDGES) return;
    int r = rows[e];
    int p = g_start[r] + atomicAdd(&g_count[r], 1);
    g_edge[p] = make_int2(cols[e], __float_as_int(vals[e]));   // one 8B store
}

// ---------------------------------------------------------------------------
// GEMM: support = x @ W   (32-row x 128-col tile, 256 threads, FFMA-bound)
// ---------------------------------------------------------------------------
__global__ __launch_bounds__(256) void gemm_kernel(const float* __restrict__ x,
                                                   const float* __restrict__ w) {
    __shared__ float xs[32][F];
    const int m0 = blockIdx.x * 32;
    const int t  = threadIdx.x;

    {
        float4* xdst = (float4*)&xs[0][0];
        const int nvec = 32 * F / 4;
        #pragma unroll
        for (int i = t; i < nvec; i += 256) {
            int row = i >> 5;
            if (m0 + row < N_NODES)
                xdst[i] = ((const float4*)(x + (size_t)m0 * F))[i];
            else
                xdst[i] = make_float4(0.f, 0.f, 0.f, 0.f);
        }
    }
    __syncthreads();

    const int q = t & 31;
    const int g = t >> 5;

    float acc[4][4];
    #pragma unroll
    for (int i = 0; i < 4; i++)
        #pragma unroll
        for (int j = 0; j < 4; j++) acc[i][j] = 0.f;

    const float4* __restrict__ w4 = (const float4*)w;

    #pragma unroll 2
    for (int k = 0; k < F; k += 4) {
        float xr[4][4];
        #pragma unroll
        for (int i = 0; i < 4; i++) {
            float4 xv = *(const float4*)&xs[g * 4 + i][k];
            xr[i][0] = xv.x; xr[i][1] = xv.y; xr[i][2] = xv.z; xr[i][3] = xv.w;
        }
        #pragma unroll
        for (int kk = 0; kk < 4; kk++) {
            float4 wv = w4[(size_t)(k + kk) * 32 + q];
            #pragma unroll
            for (int i = 0; i < 4; i++) {
                acc[i][0] += xr[i][kk] * wv.x;
                acc[i][1] += xr[i][kk] * wv.y;
                acc[i][2] += xr[i][kk] * wv.z;
                acc[i][3] += xr[i][kk] * wv.w;
            }
        }
    }

    #pragma unroll
    for (int i = 0; i < 4; i++) {
        int m = m0 + g * 4 + i;
        if (m < N_NODES) {
            float4 v = make_float4(acc[i][0], acc[i][1], acc[i][2], acc[i][3]);
            *(float4*)&g_support[(size_t)m * F + q * 4] = v;
        }
    }
}

// ---------------------------------------------------------------------------
// CSR SpMM: one warp per row, 4-edge unrolled ILP, atomic-free, bias fused.
// Edge records are read warp-uniform (broadcast); the 4 gathers per
// iteration are independent -> latency hidden, L2-traffic-bound.
// ---------------------------------------------------------------------------
__global__ __launch_bounds__(256) void spmm_csr_kernel(const float* __restrict__ bias,
                                                       float*       __restrict__ out) {
    const int warp = (blockIdx.x * blockDim.x + threadIdx.x) >> 5;
    const int lane = threadIdx.x & 31;
    if (warp >= N_NODES) return;

    const int s = g_start[warp];
    const int e = g_start[warp + 1];

    float4 acc = ((const float4*)bias)[lane];

    int base = s;
    for (; base + 4 <= e; base += 4) {
        const int2 e0 = g_edge[base + 0];
        const int2 e1 = g_edge[base + 1];
        const int2 e2 = g_edge[base + 2];
        const int2 e3 = g_edge[base + 3];
        const float4 s0 = *(const float4*)&g_support[(size_t)e0.x * F + lane * 4];
        const float4 s1 = *(const float4*)&g_support[(size_t)e1.x * F + lane * 4];
        const float4 s2 = *(const float4*)&g_support[(size_t)e2.x * F + lane * 4];
        const float4 s3 = *(const float4*)&g_support[(size_t)e3.x * F + lane * 4];
        const float v0 = __int_as_float(e0.y);
        const float v1 = __int_as_float(e1.y);
        const float v2 = __int_as_float(e2.y);
        const float v3 = __int_as_float(e3.y);
        acc.x += v0 * s0.x; acc.y += v0 * s0.y; acc.z += v0 * s0.z; acc.w += v0 * s0.w;
        acc.x += v1 * s1.x; acc.y += v1 * s1.y; acc.z += v1 * s1.z; acc.w += v1 * s1.w;
        acc.x += v2 * s2.x; acc.y += v2 * s2.y; acc.z += v2 * s2.z; acc.w += v2 * s2.w;
        acc.x += v3 * s3.x; acc.y += v3 * s3.y; acc.z += v3 * s3.z; acc.w += v3 * s3.w;
    }
    for (; base < e; base++) {
        const int2  ed = g_edge[base];
        const float4 sv = *(const float4*)&g_support[(size_t)ed.x * F + lane * 4];
        const float  v  = __int_as_float(ed.y);
        acc.x += v * sv.x; acc.y += v * sv.y; acc.z += v * sv.z; acc.w += v * sv.w;
    }

    *(float4*)&out[(size_t)warp * F + lane * 4] = acc;
}

// ---------------------------------------------------------------------------
// Launch. Inputs: 0=x, 1=weight, 2=bias, 3=edge_vals, 4=edge_rows, 5=edge_cols
// ---------------------------------------------------------------------------
extern "C" void kernel_launch(void* const* d_in, const int* in_sizes, int n_in,
                              void* d_out, int out_size) {
    const float* x    = (const float*)d_in[0];
    const float* w    = (const float*)d_in[1];
    const float* bias = (const float*)d_in[2];
    const float* vals = (const float*)d_in[3];
    const int*   rows = (const int*)d_in[4];
    const int*   cols = (const int*)d_in[5];
    float*       out  = (float*)d_out;

    // CSR build
    zero_count_kernel<<<(N_NODES + 255) / 256, 256>>>();
    hist_kernel<<<(N_EDGES + 255) / 256, 256>>>(rows);
    scan1_kernel<<<SCAN_BLOCKS, 1024>>>();
    scan2_kernel<<<1, 64>>>();
    scan3_kernel<<<SCAN_BLOCKS, 1024>>>();
    scatter_kernel<<<(N_EDGES + 255) / 256, 256>>>(rows, cols, vals);

    // support = x @ W  (overlaps nothing but is independent of CSR build order-wise;
    // stream order keeps it after scatter, which is fine)
    gemm_kernel<<<(N_NODES + 31) / 32, 256>>>(x, w);

    // out = A_csr @ support + bias
    {
        const long long threads = (long long)N_NODES * 32;
        spmm_csr_kernel<<<(int)((threads + 255) / 256), 256>>>(bias, out);
    }
}

// round 5
// speedup vs baseline: 2.1388x; 1.2525x over previous
#include <cuda_runtime.h>
#include <cuda_bf16.h>
#include <cstdint>

#define N_NODES 50000
#define N_EDGES 625000
#define F 128
#define SCAN_BLOCKS 49          // 49 * 1024 = 50176 >= N_NODES
#define TILE_M 128
#define GEMM_BLOCKS ((N_NODES + TILE_M - 1) / TILE_M)   // 391
#define SPAD 136                // padded row stride (bf16 elems) -> conflict-free LDSM
#define TILE_BYTES (128 * SPAD * 2)
#define GEMM_SMEM (4 * TILE_BYTES)                      // Ah, Al, Bh, Bl = 139264 B

// ---------------------------------------------------------------------------
// Scratch (__device__ globals => allocation-free)
// ---------------------------------------------------------------------------
__device__ float         g_support[(size_t)N_NODES * F];   // x @ W (25.6 MB)
__device__ int           g_count[N_NODES];
__device__ int           g_start[N_NODES + 1];
__device__ int2          g_edge[N_EDGES];
__device__ int           g_bsum[SCAN_BLOCKS];
__device__ int           g_boff[SCAN_BLOCKS];
__device__ __nv_bfloat16 g_wt_hi[F * F];                   // W^T hi (bf16), [n][k]
__device__ __nv_bfloat16 g_wt_lo[F * F];                   // W^T lo (bf16), [n][k]

__device__ __forceinline__ uint32_t smem_u32(const void* p) {
    uint32_t a;
    asm("{ .reg .u64 t; cvta.to.shared.u64 t, %1; cvt.u32.u64 %0, t; }" : "=r"(a) : "l"(p));
    return a;
}

#define LDSM4(r0, r1, r2, r3, addr)                                              \
    asm volatile("ldmatrix.sync.aligned.m8n8.x4.shared.b16 {%0,%1,%2,%3}, [%4];" \
                 : "=r"(r0), "=r"(r1), "=r"(r2), "=r"(r3) : "r"(addr))

#define MMA16816(c, a0, a1, a2, a3, b0, b1)                                      \
    asm volatile("mma.sync.aligned.m16n8k16.row.col.f32.bf16.bf16.f32 "          \
                 "{%0,%1,%2,%3}, {%4,%5,%6,%7}, {%8,%9}, {%0,%1,%2,%3};"         \
                 : "+f"((c)[0]), "+f"((c)[1]), "+f"((c)[2]), "+f"((c)[3])        \
                 : "r"(a0), "r"(a1), "r"(a2), "r"(a3), "r"(b0), "r"(b1))

// ---------------------------------------------------------------------------
// CSR build
// ---------------------------------------------------------------------------
__global__ void zero_count_kernel() {
    int i = blockIdx.x * blockDim.x + threadIdx.x;
    if (i < N_NODES) g_count[i] = 0;
}

__global__ void hist_kernel(const int* __restrict__ rows) {
    int e = blockIdx.x * blockDim.x + threadIdx.x;
    if (e < N_EDGES) atomicAdd(&g_count[rows[e]], 1);
}

__global__ __launch_bounds__(1024) void scan1_kernel() {
    __shared__ int sm[1024];
    const int t   = threadIdx.x;
    const int idx = blockIdx.x * 1024 + t;
    const int v   = (idx < N_NODES) ? g_count[idx] : 0;
    sm[t] = v;
    __syncthreads();
    #pragma unroll
    for (int off = 1; off < 1024; off <<= 1) {
        int add = (t >= off) ? sm[t - off] : 0;
        __syncthreads();
        if (t >= off) sm[t] += add;
        __syncthreads();
    }
    if (idx < N_NODES) g_start[idx] = sm[t] - v;
    if (t == 1023) g_bsum[blockIdx.x] = sm[1023];
}

__global__ __launch_bounds__(64) void scan2_kernel() {
    __shared__ int sm[64];
    const int t = threadIdx.x;
    const int v = (t < SCAN_BLOCKS) ? g_bsum[t] : 0;
    sm[t] = v;
    __syncthreads();
    #pragma unroll
    for (int off = 1; off < 64; off <<= 1) {
        int add = (t >= off) ? sm[t - off] : 0;
        __syncthreads();
        if (t >= off) sm[t] += add;
        __syncthreads();
    }
    if (t < SCAN_BLOCKS) g_boff[t] = sm[t] - v;
}

__global__ __launch_bounds__(1024) void scan3_kernel() {
    const int idx = blockIdx.x * 1024 + threadIdx.x;
    if (idx < N_NODES) {
        g_start[idx] += g_boff[blockIdx.x];
        g_count[idx] = 0;
    }
    if (idx == 0) g_start[N_NODES] = N_EDGES;
}

__global__ void scatter_kernel(const int*   __restrict__ rows,
                               const int*   __restrict__ cols,
                               const float* __restrict__ vals) {
    int e = blockIdx.x * blockDim.x + threadIdx.x;
    if (e >= N_EDGES) return;
    int r = rows[e];
    int p = g_start[r] + atomicAdd(&g_count[r], 1);
    g_edge[p] = make_int2(cols[e], __float_as_int(vals[e]));
}

// ---------------------------------------------------------------------------
// W^T hi/lo split (bf16): WtHi[n][k] + WtLo[n][k] ~= W[k][n]
// ---------------------------------------------------------------------------
__global__ void prep_w_kernel(const float* __restrict__ w) {
    int i = blockIdx.x * blockDim.x + threadIdx.x;   // i = n*F + k
    if (i >= F * F) return;
    int n = i >> 7, k = i & 127;
    float v = w[k * F + n];
    __nv_bfloat16 h = __float2bfloat16(v);
    g_wt_hi[i] = h;
    g_wt_lo[i] = __float2bfloat16(v - __bfloat162float(h));
}

// ---------------------------------------------------------------------------
// Tensor-core GEMM via mma.sync (HMMA bf16, split-3):
//   support = x @ W  with  AhBh + AhBl + AlBh
// 256 threads, 128x128 tile/block; warp w owns rows [16w, 16w+16).
// ---------------------------------------------------------------------------
__global__ __launch_bounds__(256, 1) void gemm_mma_kernel(const float* __restrict__ x) {
    extern __shared__ char smem[];
    __nv_bfloat16* sAh = (__nv_bfloat16*)smem;                 // 128 x SPAD
    __nv_bfloat16* sAl = sAh + 128 * SPAD;
    __nv_bfloat16* sBh = sAl + 128 * SPAD;
    __nv_bfloat16* sBl = sBh + 128 * SPAD;

    const int t  = threadIdx.x;
    const int m0 = blockIdx.x * TILE_M;

    // ---- Load + split x tile into smem (hi/lo bf16), padded stride ----
    #pragma unroll 4
    for (int i = 0; i < 16; i++) {
        int idx = t + 256 * i;                 // 4096 float4 slots
        int row = idx >> 5;
        int c4  = (idx & 31) * 4;
        int m   = m0 + row;
        float4 xv = (m < N_NODES) ? ((const float4*)x)[((size_t)m * F + c4) >> 2]
                                  : make_float4(0.f, 0.f, 0.f, 0.f);
        __nv_bfloat16 h0 = __float2bfloat16(xv.x);
        __nv_bfloat16 h1 = __float2bfloat16(xv.y);
        __nv_bfloat16 h2 = __float2bfloat16(xv.z);
        __nv_bfloat16 h3 = __float2bfloat16(xv.w);
        __nv_bfloat16 l0 = __float2bfloat16(xv.x - __bfloat162float(h0));
        __nv_bfloat16 l1 = __float2bfloat16(xv.y - __bfloat162float(h1));
        __nv_bfloat16 l2 = __float2bfloat16(xv.z - __bfloat162float(h2));
        __nv_bfloat16 l3 = __float2bfloat16(xv.w - __bfloat162float(h3));
        uint2 hi, lo;
        hi.x = (uint32_t)__bfloat16_as_ushort(h0) | ((uint32_t)__bfloat16_as_ushort(h1) << 16);
        hi.y = (uint32_t)__bfloat16_as_ushort(h2) | ((uint32_t)__bfloat16_as_ushort(h3) << 16);
        lo.x = (uint32_t)__bfloat16_as_ushort(l0) | ((uint32_t)__bfloat16_as_ushort(l1) << 16);
        lo.y = (uint32_t)__bfloat16_as_ushort(l2) | ((uint32_t)__bfloat16_as_ushort(l3) << 16);
        int off = row * SPAD + c4;
        *(uint2*)&sAh[off] = hi;
        *(uint2*)&sAl[off] = lo;
    }

    // ---- Copy pre-split W^T into smem, padded stride ----
    #pragma unroll 4
    for (int i = 0; i < 16; i++) {
        int idx = t + 256 * i;
        int row = idx >> 5;
        int c4  = (idx & 31) * 4;
        int off = row * SPAD + c4;
        *(uint2*)&sBh[off] = *(const uint2*)&g_wt_hi[row * F + c4];
        *(uint2*)&sBl[off] = *(const uint2*)&g_wt_lo[row * F + c4];
    }
    __syncthreads();

    const int wid  = t >> 5;
    const int lane = t & 31;
    const int R    = wid * 16;

    float acc[16][4];
    #pragma unroll
    for (int i = 0; i < 16; i++)
        #pragma unroll
        for (int j = 0; j < 4; j++) acc[i][j] = 0.f;

    const uint32_t base   = smem_u32(smem);
    const uint32_t aHbase = base;
    const uint32_t aLbase = base + TILE_BYTES;
    const uint32_t bHbase = base + 2 * TILE_BYTES;
    const uint32_t bLbase = base + 3 * TILE_BYTES;

    // ldmatrix lane->address mapping
    const int arow      = R + (lane & 7) + ((lane >> 3) & 1) * 8;  // A: grp0/2 rows, grp1/3 rows+8
    const int acolh     = (lane >> 4) * 8;                          // A: grp2/3 -> k+8
    const int brow_in   = (lane & 7) + ((lane >= 16) ? 8 : 0);      // B: grp2/3 -> n+8
    const int bcolh     = ((lane >> 3) & 1) * 8;                    // B: grp1/3 -> k+8

    #pragma unroll 1
    for (int kc = 0; kc < 8; kc++) {
        const int k0 = kc * 16;
        const uint32_t aoff = (uint32_t)((arow * SPAD + k0 + acolh) * 2);
        uint32_t ah0, ah1, ah2, ah3, al0, al1, al2, al3;
        LDSM4(ah0, ah1, ah2, ah3, aHbase + aoff);
        LDSM4(al0, al1, al2, al3, aLbase + aoff);

        #pragma unroll
        for (int np = 0; np < 8; np++) {            // ntile pair: cols [np*16, np*16+16)
            const uint32_t boff = (uint32_t)(((np * 16 + brow_in) * SPAD + k0 + bcolh) * 2);
            uint32_t bh0, bh1, bh2, bh3, bl0, bl1, bl2, bl3;
            LDSM4(bh0, bh1, bh2, bh3, bHbase + boff);
            LDSM4(bl0, bl1, bl2, bl3, bLbase + boff);
            MMA16816(acc[2 * np],     ah0, ah1, ah2, ah3, bh0, bh1);
            MMA16816(acc[2 * np + 1], ah0, ah1, ah2, ah3, bh2, bh3);
            MMA16816(acc[2 * np],     ah0, ah1, ah2, ah3, bl0, bl1);
            MMA16816(acc[2 * np + 1], ah0, ah1, ah2, ah3, bl2, bl3);
            MMA16816(acc[2 * np],     al0, al1, al2, al3, bh0, bh1);
            MMA16816(acc[2 * np + 1], al0, al1, al2, al3, bh2, bh3);
        }
    }

    // ---- Epilogue: accum regs -> g_support (float2, full 32B sectors) ----
    const int g   = lane >> 2;
    const int tig = lane & 3;
    const int m1  = m0 + R + g;
    const int m2  = m1 + 8;
    #pragma unroll
    for (int nt = 0; nt < 16; nt++) {
        const int c = nt * 8 + tig * 2;
        if (m1 < N_NODES)
            *(float2*)&g_support[(size_t)m1 * F + c] = make_float2(acc[nt][0], acc[nt][1]);
        if (m2 < N_NODES)
            *(float2*)&g_support[(size_t)m2 * F + c] = make_float2(acc[nt][2], acc[nt][3]);
    }
}

// ---------------------------------------------------------------------------
// CSR SpMM: warp per row, 4-edge ILP, atomic-free, bias fused
// ---------------------------------------------------------------------------
__global__ __launch_bounds__(256) void spmm_csr_kernel(const float* __restrict__ bias,
                                                       float*       __restrict__ out) {
    const int warp = (blockIdx.x * blockDim.x + threadIdx.x) >> 5;
    const int lane = threadIdx.x & 31;
    if (warp >= N_NODES) return;

    const int s = g_start[warp];
    const int e = g_start[warp + 1];

    float4 acc = ((const float4*)bias)[lane];

    int base = s;
    for (; base + 4 <= e; base += 4) {
        const int2 e0 = g_edge[base + 0];
        const int2 e1 = g_edge[base + 1];
        const int2 e2 = g_edge[base + 2];
        const int2 e3 = g_edge[base + 3];
        const float4 s0 = *(const float4*)&g_support[(size_t)e0.x * F + lane * 4];
        const float4 s1 = *(const float4*)&g_support[(size_t)e1.x * F + lane * 4];
        const float4 s2 = *(const float4*)&g_support[(size_t)e2.x * F + lane * 4];
        const float4 s3 = *(const float4*)&g_support[(size_t)e3.x * F + lane * 4];
        const float v0 = __int_as_float(e0.y);
        const float v1 = __int_as_float(e1.y);
        const float v2 = __int_as_float(e2.y);
        const float v3 = __int_as_float(e3.y);
        acc.x += v0 * s0.x; acc.y += v0 * s0.y; acc.z += v0 * s0.z; acc.w += v0 * s0.w;
        acc.x += v1 * s1.x; acc.y += v1 * s1.y; acc.z += v1 * s1.z; acc.w += v1 * s1.w;
        acc.x += v2 * s2.x; acc.y += v2 * s2.y; acc.z += v2 * s2.z; acc.w += v2 * s2.w;
        acc.x += v3 * s3.x; acc.y += v3 * s3.y; acc.z += v3 * s3.z; acc.w += v3 * s3.w;
    }
    for (; base < e; base++) {
        const int2  ed = g_edge[base];
        const float4 sv = *(const float4*)&g_support[(size_t)ed.x * F + lane * 4];
        const float  v  = __int_as_float(ed.y);
        acc.x += v * sv.x; acc.y += v * sv.y; acc.z += v * sv.z; acc.w += v * sv.w;
    }

    *(float4*)&out[(size_t)warp * F + lane * 4] = acc;
}

// ---------------------------------------------------------------------------
// Launch. Inputs: 0=x, 1=weight, 2=bias, 3=edge_vals, 4=edge_rows, 5=edge_cols
// ---------------------------------------------------------------------------
extern "C" void kernel_launch(void* const* d_in, const int* in_sizes, int n_in,
                              void* d_out, int out_size) {
    const float* x    = (const float*)d_in[0];
    const float* w    = (const float*)d_in[1];
    const float* bias = (const float*)d_in[2];
    const float* vals = (const float*)d_in[3];
    const int*   rows = (const int*)d_in[4];
    const int*   cols = (const int*)d_in[5];
    float*       out  = (float*)d_out;

    static bool attr_set = false;
    if (!attr_set) {
        cudaFuncSetAttribute(gemm_mma_kernel,
                             cudaFuncAttributeMaxDynamicSharedMemorySize, GEMM_SMEM);
        attr_set = true;
    }

    // CSR build
    zero_count_kernel<<<(N_NODES + 255) / 256, 256>>>();
    hist_kernel<<<(N_EDGES + 255) / 256, 256>>>(rows);
    scan1_kernel<<<SCAN_BLOCKS, 1024>>>();
    scan2_kernel<<<1, 64>>>();
    scan3_kernel<<<SCAN_BLOCKS, 1024>>>();
    scatter_kernel<<<(N_EDGES + 255) / 256, 256>>>(rows, cols, vals);

    // support = x @ W  (HMMA bf16 split-3)
    prep_w_kernel<<<(F * F + 255) / 256, 256>>>(w);
    gemm_mma_kernel<<<GEMM_BLOCKS, 256, GEMM_SMEM>>>(x);

    // out = A_csr @ support + bias
    {
        const long long threads = (long long)N_NODES * 32;
        spmm_csr_kernel<<<(int)((threads + 255) / 256), 256>>>(bias, out);
    }
}

// round 8
// speedup vs baseline: 2.3130x; 1.0814x over previous
#include <cuda_runtime.h>
#include <cuda_bf16.h>
#include <cstdint>

#define N_NODES 50000
#define N_EDGES 625000
#define F 128
#define SCAN_BLOCKS 49          // 49 * 1024 = 50176 >= N_NODES
#define TILE_M 128
#define GEMM_BLOCKS ((N_NODES + TILE_M - 1) / TILE_M)   // 391
#define SPAD 136                // padded row stride (bf16 elems) -> conflict-free LDSM
#define TILE_BYTES (128 * SPAD * 2)
#define GEMM_SMEM (4 * TILE_BYTES)                      // Ah, Al, Bh, Bl = 139264 B
#define AGG_FLAG (1 << 30)

// ---------------------------------------------------------------------------
// Scratch (__device__ globals => allocation-free)
// Invariant: g_count[] == 0 at entry of every kernel_launch call.
//   - zero-initialized at module load (first call)
//   - scatter_kernel's atomicSub cursor returns every element to 0 each call
// ---------------------------------------------------------------------------
__device__ float         g_support[(size_t)N_NODES * F];   // x @ W (25.6 MB)
__device__ int           g_count[N_NODES];                 // histogram / cursor
__device__ int           g_start[N_NODES + 1];             // CSR row starts
__device__ int2          g_edge[N_EDGES];                  // packed {col, val} by row
__device__ int           g_agg[SCAN_BLOCKS];               // lookback aggregates
__device__ __nv_bfloat16 g_wt_hi[F * F];                   // W^T hi (bf16), [n][k]
__device__ __nv_bfloat16 g_wt_lo[F * F];                   // W^T lo (bf16), [n][k]

__device__ __forceinline__ uint32_t smem_u32(const void* p) {
    uint32_t a;
    asm("{ .reg .u64 t; cvta.to.shared.u64 t, %1; cvt.u32.u64 %0, t; }" : "=r"(a) : "l"(p));
    return a;
}

#define LDSM4(r0, r1, r2, r3, addr)                                              \
    asm volatile("ldmatrix.sync.aligned.m8n8.x4.shared.b16 {%0,%1,%2,%3}, [%4];" \
                 : "=r"(r0), "=r"(r1), "=r"(r2), "=r"(r3) : "r"(addr))

#define MMA16816(c, a0, a1, a2, a3, b0, b1)                                      \
    asm volatile("mma.sync.aligned.m16n8k16.row.col.f32.bf16.bf16.f32 "          \
                 "{%0,%1,%2,%3}, {%4,%5,%6,%7}, {%8,%9}, {%0,%1,%2,%3};"         \
                 : "+f"((c)[0]), "+f"((c)[1]), "+f"((c)[2]), "+f"((c)[3])        \
                 : "r"(a0), "r"(a1), "r"(a2), "r"(a3), "r"(b0), "r"(b1))

// ---------------------------------------------------------------------------
// Kernel 1: histogram of edge rows  (+ fused: W^T hi/lo split, agg-flag reset)
// ---------------------------------------------------------------------------
__global__ void hist_kernel(const int* __restrict__ rows, const float* __restrict__ w) {
    const int gid = blockIdx.x * blockDim.x + threadIdx.x;
    if (gid < N_EDGES) atomicAdd(&g_count[rows[gid]], 1);
    if (gid < SCAN_BLOCKS) g_agg[gid] = 0;
    if (gid < F * F) {
        // gid = n*F + k ; W stored [k][n]
        int n = gid >> 7, k = gid & 127;
        float v = w[k * F + n];
        __nv_bfloat16 h = __float2bfloat16(v);
        g_wt_hi[gid] = h;
        g_wt_lo[gid] = __float2bfloat16(v - __bfloat162float(h));
    }
}

// ---------------------------------------------------------------------------
// Kernel 2: single-pass exclusive scan of g_count -> g_start
// 49 co-resident blocks; decoupled lookback via flagged aggregates.
// FIX vs R6: lookback strides over ALL predecessors (p = lane; p < bid; p += 32)
// instead of only lanes 0..31 — blocks 33..48 were missing aggregates.
// ---------------------------------------------------------------------------
__global__ __launch_bounds__(1024) void scan_fused_kernel() {
    __shared__ int wsum[32];
    __shared__ int blk_prev;
    const int t    = threadIdx.x;
    const int bid  = blockIdx.x;
    const int lane = t & 31;
    const int wid  = t >> 5;
    const int idx  = bid * 1024 + t;

    const int v = (idx < N_NODES) ? g_count[idx] : 0;

    // warp inclusive scan
    int s = v;
    #pragma unroll
    for (int off = 1; off < 32; off <<= 1) {
        int n = __shfl_up_sync(0xffffffffu, s, off);
        if (lane >= off) s += n;
    }
    if (lane == 31) wsum[wid] = s;
    __syncthreads();

    if (wid == 0) {
        // scan the 32 warp totals
        int ws = wsum[lane];
        #pragma unroll
        for (int off = 1; off < 32; off <<= 1) {
            int n = __shfl_up_sync(0xffffffffu, ws, off);
            if (lane >= off) ws += n;
        }
        wsum[lane] = ws;
        if (lane == 31) atomicExch(&g_agg[bid], ws | AGG_FLAG);  // publish chunk total

        // parallel lookback over ALL predecessors (strided by warp width)
        int a = 0;
        for (int p = lane; p < bid; p += 32) {
            volatile int* agg = g_agg;
            int xv;
            do { xv = agg[p]; } while (!(xv & AGG_FLAG));
            a += xv & (AGG_FLAG - 1);
        }
        #pragma unroll
        for (int off = 16; off >= 1; off >>= 1)
            a += __shfl_xor_sync(0xffffffffu, a, off);
        if (lane == 0) blk_prev = a;
    }
    __syncthreads();

    const int wexcl = (wid > 0) ? wsum[wid - 1] : 0;
    if (idx < N_NODES) g_start[idx] = blk_prev + wexcl + (s - v);
    if (idx == 0) g_start[N_NODES] = N_EDGES;
}

// ---------------------------------------------------------------------------
// Kernel 3: scatter edges into CSR order.
// Cursor counts DOWN via atomicSub -> g_count returns to all-zero (invariant).
// ---------------------------------------------------------------------------
__global__ void scatter_kernel(const int*   __restrict__ rows,
                               const int*   __restrict__ cols,
                               const float* __restrict__ vals) {
    int e = blockIdx.x * blockDim.x + threadIdx.x;
    if (e >= N_EDGES) return;
    int r = rows[e];
    int p = g_start[r] + atomicSub(&g_count[r], 1) - 1;
    g_edge[p] = make_int2(cols[e], __float_as_int(vals[e]));
}

// ---------------------------------------------------------------------------
// Kernel 4: tensor-core GEMM via mma.sync (HMMA bf16, split-3):
//   support = x @ W  with  AhBh + AhBl + AlBh
// 256 threads, 128x128 tile/block; warp w owns rows [16w, 16w+16).
// ---------------------------------------------------------------------------
__global__ __launch_bounds__(256, 1) void gemm_mma_kernel(const float* __restrict__ x) {
    extern __shared__ char smem[];
    __nv_bfloat16* sAh = (__nv_bfloat16*)smem;                 // 128 x SPAD
    __nv_bfloat16* sAl = sAh + 128 * SPAD;
    __nv_bfloat16* sBh = sAl + 128 * SPAD;
    __nv_bfloat16* sBl = sBh + 128 * SPAD;

    const int t  = threadIdx.x;
    const int m0 = blockIdx.x * TILE_M;

    // ---- Load + split x tile into smem (hi/lo bf16), padded stride ----
    #pragma unroll 4
    for (int i = 0; i < 16; i++) {
        int idx = t + 256 * i;                 // 4096 float4 slots
        int row = idx >> 5;
        int c4  = (idx & 31) * 4;
        int m   = m0 + row;
        float4 xv = (m < N_NODES) ? ((const float4*)x)[((size_t)m * F + c4) >> 2]
                                  : make_float4(0.f, 0.f, 0.f, 0.f);
        __nv_bfloat16 h0 = __float2bfloat16(xv.x);
        __nv_bfloat16 h1 = __float2bfloat16(xv.y);
        __nv_bfloat16 h2 = __float2bfloat16(xv.z);
        __nv_bfloat16 h3 = __float2bfloat16(xv.w);
        __nv_bfloat16 l0 = __float2bfloat16(xv.x - __bfloat162float(h0));
        __nv_bfloat16 l1 = __float2bfloat16(xv.y - __bfloat162float(h1));
        __nv_bfloat16 l2 = __float2bfloat16(xv.z - __bfloat162float(h2));
        __nv_bfloat16 l3 = __float2bfloat16(xv.w - __bfloat162float(h3));
        uint2 hi, lo;
        hi.x = (uint32_t)__bfloat16_as_ushort(h0) | ((uint32_t)__bfloat16_as_ushort(h1) << 16);
        hi.y = (uint32_t)__bfloat16_as_ushort(h2) | ((uint32_t)__bfloat16_as_ushort(h3) << 16);
        lo.x = (uint32_t)__bfloat16_as_ushort(l0) | ((uint32_t)__bfloat16_as_ushort(l1) << 16);
        lo.y = (uint32_t)__bfloat16_as_ushort(l2) | ((uint32_t)__bfloat16_as_ushort(l3) << 16);
        int off = row * SPAD + c4;
        *(uint2*)&sAh[off] = hi;
        *(uint2*)&sAl[off] = lo;
    }

    // ---- Copy pre-split W^T into smem, padded stride ----
    #pragma unroll 4
    for (int i = 0; i < 16; i++) {
        int idx = t + 256 * i;
        int row = idx >> 5;
        int c4  = (idx & 31) * 4;
        int off = row * SPAD + c4;
        *(uint2*)&sBh[off] = *(const uint2*)&g_wt_hi[row * F + c4];
        *(uint2*)&sBl[off] = *(const uint2*)&g_wt_lo[row * F + c4];
    }
    __syncthreads();

    const int wid  = t >> 5;
    const int lane = t & 31;
    const int R    = wid * 16;

    float acc[16][4];
    #pragma unroll
    for (int i = 0; i < 16; i++)
        #pragma unroll
        for (int j = 0; j < 4; j++) acc[i][j] = 0.f;

    const uint32_t base   = smem_u32(smem);
    const uint32_t aHbase = base;
    const uint32_t aLbase = base + TILE_BYTES;
    const uint32_t bHbase = base + 2 * TILE_BYTES;
    const uint32_t bLbase = base + 3 * TILE_BYTES;

    const int arow    = R + (lane & 7) + ((lane >> 3) & 1) * 8;
    const int acolh   = (lane >> 4) * 8;
    const int brow_in = (lane & 7) + ((lane >= 16) ? 8 : 0);
    const int bcolh   = ((lane >> 3) & 1) * 8;

    #pragma unroll 1
    for (int kc = 0; kc < 8; kc++) {
        const int k0 = kc * 16;
        const uint32_t aoff = (uint32_t)((arow * SPAD + k0 + acolh) * 2);
        uint32_t ah0, ah1, ah2, ah3, al0, al1, al2, al3;
        LDSM4(ah0, ah1, ah2, ah3, aHbase + aoff);
        LDSM4(al0, al1, al2, al3, aLbase + aoff);

        #pragma unroll
        for (int np = 0; np < 8; np++) {
            const uint32_t boff = (uint32_t)(((np * 16 + brow_in) * SPAD + k0 + bcolh) * 2);
            uint32_t bh0, bh1, bh2, bh3, bl0, bl1, bl2, bl3;
            LDSM4(bh0, bh1, bh2, bh3, bHbase + boff);
            LDSM4(bl0, bl1, bl2, bl3, bLbase + boff);
            MMA16816(acc[2 * np],     ah0, ah1, ah2, ah3, bh0, bh1);
            MMA16816(acc[2 * np + 1], ah0, ah1, ah2, ah3, bh2, bh3);
            MMA16816(acc[2 * np],     ah0, ah1, ah2, ah3, bl0, bl1);
            MMA16816(acc[2 * np + 1], ah0, ah1, ah2, ah3, bl2, bl3);
            MMA16816(acc[2 * np],     al0, al1, al2, al3, bh0, bh1);
            MMA16816(acc[2 * np + 1], al0, al1, al2, al3, bh2, bh3);
        }
    }

    // ---- Epilogue: accum regs -> g_support (float2, full 32B sectors) ----
    const int g   = lane >> 2;
    const int tig = lane & 3;
    const int m1  = m0 + R + g;
    const int m2  = m1 + 8;
    #pragma unroll
    for (int nt = 0; nt < 16; nt++) {
        const int c = nt * 8 + tig * 2;
        if (m1 < N_NODES)
            *(float2*)&g_support[(size_t)m1 * F + c] = make_float2(acc[nt][0], acc[nt][1]);
        if (m2 < N_NODES)
            *(float2*)&g_support[(size_t)m2 * F + c] = make_float2(acc[nt][2], acc[nt][3]);
    }
}

// ---------------------------------------------------------------------------
// Kernel 5: CSR SpMM: warp per row, 4-edge ILP, atomic-free, bias fused
// ---------------------------------------------------------------------------
__global__ __launch_bounds__(256) void spmm_csr_kernel(const float* __restrict__ bias,
                                                       float*       __restrict__ out) {
    const int warp = (blockIdx.x * blockDim.x + threadIdx.x) >> 5;
    const int lane = threadIdx.x & 31;
    if (warp >= N_NODES) return;

    const int s = g_start[warp];
    const int e = g_start[warp + 1];

    float4 acc = ((const float4*)bias)[lane];

    int base = s;
    for (; base + 4 <= e; base += 4) {
        const int2 e0 = g_edge[base + 0];
        const int2 e1 = g_edge[base + 1];
        const int2 e2 = g_edge[base + 2];
        const int2 e3 = g_edge[base + 3];
        const float4 s0 = *(const float4*)&g_support[(size_t)e0.x * F + lane * 4];
        const float4 s1 = *(const float4*)&g_support[(size_t)e1.x * F + lane * 4];
        const float4 s2 = *(const float4*)&g_support[(size_t)e2.x * F + lane * 4];
        const float4 s3 = *(const float4*)&g_support[(size_t)e3.x * F + lane * 4];
        const float v0 = __int_as_float(e0.y);
        const float v1 = __int_as_float(e1.y);
        const float v2 = __int_as_float(e2.y);
        const float v3 = __int_as_float(e3.y);
        acc.x += v0 * s0.x; acc.y += v0 * s0.y; acc.z += v0 * s0.z; acc.w += v0 * s0.w;
        acc.x += v1 * s1.x; acc.y += v1 * s1.y; acc.z += v1 * s1.z; acc.w += v1 * s1.w;
        acc.x += v2 * s2.x; acc.y += v2 * s2.y; acc.z += v2 * s2.z; acc.w += v2 * s2.w;
        acc.x += v3 * s3.x; acc.y += v3 * s3.y; acc.z += v3 * s3.z; acc.w += v3 * s3.w;
    }
    for (; base < e; base++) {
        const int2  ed = g_edge[base];
        const float4 sv = *(const float4*)&g_support[(size_t)ed.x * F + lane * 4];
        const float  v  = __int_as_float(ed.y);
        acc.x += v * sv.x; acc.y += v * sv.y; acc.z += v * sv.z; acc.w += v * sv.w;
    }

    *(float4*)&out[(size_t)warp * F + lane * 4] = acc;
}

// ---------------------------------------------------------------------------
// Launch. Inputs: 0=x, 1=weight, 2=bias, 3=edge_vals, 4=edge_rows, 5=edge_cols
// ---------------------------------------------------------------------------
extern "C" void kernel_launch(void* const* d_in, const int* in_sizes, int n_in,
                              void* d_out, int out_size) {
    const float* x    = (const float*)d_in[0];
    const float* w    = (const float*)d_in[1];
    const float* bias = (const float*)d_in[2];
    const float* vals = (const float*)d_in[3];
    const int*   rows = (const int*)d_in[4];
    const int*   cols = (const int*)d_in[5];
    float*       out  = (float*)d_out;

    static bool attr_set = false;
    if (!attr_set) {
        cudaFuncSetAttribute(gemm_mma_kernel,
                             cudaFuncAttributeMaxDynamicSharedMemorySize, GEMM_SMEM);
        attr_set = true;
    }

    // 1) histogram (+ W split + lookback-flag reset)
    hist_kernel<<<(N_EDGES + 255) / 256, 256>>>(rows, w);
    // 2) single-pass scan -> g_start
    scan_fused_kernel<<<SCAN_BLOCKS, 1024>>>();
    // 3) scatter into CSR order (cursor decrements back to 0)
    scatter_kernel<<<(N_EDGES + 255) / 256, 256>>>(rows, cols, vals);
    // 4) support = x @ W  (HMMA bf16 split-3)
    gemm_mma_kernel<<<GEMM_BLOCKS, 256, GEMM_SMEM>>>(x);
    // 5) out = A_csr @ support + bias
    {
        const long long threads = (long long)N_NODES * 32;
        spmm_csr_kernel<<<(int)((threads + 255) / 256), 256>>>(bias, out);
    }
}

// round 9
// speedup vs baseline: 2.3824x; 1.0300x over previous
#include <cuda_runtime.h>
#include <cuda_bf16.h>
#include <cstdint>

#define N_NODES 50000
#define N_EDGES 625000
#define F 128
#define SCAN_BLOCKS 49          // 49 * 1024 = 50176 >= N_NODES
#define TILE_M 128
#define GEMM_BLOCKS ((N_NODES + TILE_M - 1) / TILE_M)   // 391
#define GEMM_THREADS 512
#define SPAD 136                // padded row stride (bf16 elems) -> conflict-free LDSM
#define TILE_BYTES (128 * SPAD * 2)
#define GEMM_SMEM (4 * TILE_BYTES)                      // Ah, Al, Bh, Bl = 139264 B
#define AGG_FLAG (1 << 30)

// ---------------------------------------------------------------------------
// Scratch (__device__ globals => allocation-free)
// Invariant: g_count[] == 0 at entry of every kernel_launch call.
//   - zero-initialized at module load (first call)
//   - scatter_kernel's atomicSub cursor returns every element to 0 each call
// ---------------------------------------------------------------------------
__device__ float g_support[(size_t)N_NODES * F];   // x @ W (25.6 MB)
__device__ int   g_count[N_NODES];                 // histogram / cursor
__device__ int   g_start[N_NODES + 1];             // CSR row starts
__device__ int2  g_edge[N_EDGES];                  // packed {col, val} by row
__device__ int   g_agg[SCAN_BLOCKS];               // lookback aggregates

__device__ __forceinline__ uint32_t smem_u32(const void* p) {
    uint32_t a;
    asm("{ .reg .u64 t; cvta.to.shared.u64 t, %1; cvt.u32.u64 %0, t; }" : "=r"(a) : "l"(p));
    return a;
}

#define LDSM4(r0, r1, r2, r3, addr)                                              \
    asm volatile("ldmatrix.sync.aligned.m8n8.x4.shared.b16 {%0,%1,%2,%3}, [%4];" \
                 : "=r"(r0), "=r"(r1), "=r"(r2), "=r"(r3) : "r"(addr))

#define MMA16816(c, a0, a1, a2, a3, b0, b1)                                      \
    asm volatile("mma.sync.aligned.m16n8k16.row.col.f32.bf16.bf16.f32 "          \
                 "{%0,%1,%2,%3}, {%4,%5,%6,%7}, {%8,%9}, {%0,%1,%2,%3};"         \
                 : "+f"((c)[0]), "+f"((c)[1]), "+f"((c)[2]), "+f"((c)[3])        \
                 : "r"(a0), "r"(a1), "r"(a2), "r"(a3), "r"(b0), "r"(b1))

// ---------------------------------------------------------------------------
// Kernel 1: GEMM (HMMA bf16 split-3) + fused edge histogram + flag reset
//   support = x @ W  with  AhBh + AhBl + AlBh
// 512 threads; warp w owns rows [16*(w>>1), +16) x cols [64*(w&1), +64).
// ---------------------------------------------------------------------------
__global__ __launch_bounds__(GEMM_THREADS, 1)
void gemm_hist_kernel(const float* __restrict__ x, const float* __restrict__ w,
                      const int* __restrict__ rows) {
    extern __shared__ char smem[];
    __nv_bfloat16* sAh = (__nv_bfloat16*)smem;                 // 128 x SPAD
    __nv_bfloat16* sAl = sAh + 128 * SPAD;
    __nv_bfloat16* sBh = sAl + 128 * SPAD;
    __nv_bfloat16* sBl = sBh + 128 * SPAD;

    const int t  = threadIdx.x;
    const int m0 = blockIdx.x * TILE_M;
    const int gid = blockIdx.x * GEMM_THREADS + t;

    // ---- Fused: edge-row histogram (fills idle issue slots) ----
    for (int e = gid; e < N_EDGES; e += GEMM_BLOCKS * GEMM_THREADS)
        atomicAdd(&g_count[rows[e]], 1);
    if (gid < SCAN_BLOCKS) g_agg[gid] = 0;

    // ---- Load + split x tile into smem (hi/lo bf16), padded stride ----
    #pragma unroll 4
    for (int i = 0; i < 8; i++) {
        int idx = t + GEMM_THREADS * i;        // 4096 float4 slots
        int row = idx >> 5;
        int c4  = (idx & 31) * 4;
        int m   = m0 + row;
        float4 xv = (m < N_NODES) ? ((const float4*)x)[((size_t)m * F + c4) >> 2]
                                  : make_float4(0.f, 0.f, 0.f, 0.f);
        __nv_bfloat16 h0 = __float2bfloat16(xv.x);
        __nv_bfloat16 h1 = __float2bfloat16(xv.y);
        __nv_bfloat16 h2 = __float2bfloat16(xv.z);
        __nv_bfloat16 h3 = __float2bfloat16(xv.w);
        __nv_bfloat16 l0 = __float2bfloat16(xv.x - __bfloat162float(h0));
        __nv_bfloat16 l1 = __float2bfloat16(xv.y - __bfloat162float(h1));
        __nv_bfloat16 l2 = __float2bfloat16(xv.z - __bfloat162float(h2));
        __nv_bfloat16 l3 = __float2bfloat16(xv.w - __bfloat162float(h3));
        uint2 hi, lo;
        hi.x = (uint32_t)__bfloat16_as_ushort(h0) | ((uint32_t)__bfloat16_as_ushort(h1) << 16);
        hi.y = (uint32_t)__bfloat16_as_ushort(h2) | ((uint32_t)__bfloat16_as_ushort(h3) << 16);
        lo.x = (uint32_t)__bfloat16_as_ushort(l0) | ((uint32_t)__bfloat16_as_ushort(l1) << 16);
        lo.y = (uint32_t)__bfloat16_as_ushort(l2) | ((uint32_t)__bfloat16_as_ushort(l3) << 16);
        int off = row * SPAD + c4;
        *(uint2*)&sAh[off] = hi;
        *(uint2*)&sAl[off] = lo;
    }

    // ---- W -> smem transposed + hi/lo split (B operand, [n][k]) ----
    #pragma unroll 4
    for (int i = 0; i < 32; i++) {
        int idx = t + GEMM_THREADS * i;        // 16384 elements, idx = k*128 + n
        int k = idx >> 7, n = idx & 127;
        float v = w[idx];                      // coalesced
        __nv_bfloat16 h = __float2bfloat16(v);
        __nv_bfloat16 l = __float2bfloat16(v - __bfloat162float(h));
        sBh[n * SPAD + k] = h;
        sBl[n * SPAD + k] = l;
    }
    __syncthreads();

    const int wid  = t >> 5;
    const int lane = t & 31;
    const int R    = (wid >> 1) * 16;          // row base within tile
    const int C0   = (wid & 1) * 64;           // col base

    float acc[8][4];
    #pragma unroll
    for (int i = 0; i < 8; i++)
        #pragma unroll
        for (int j = 0; j < 4; j++) acc[i][j] = 0.f;

    const uint32_t base   = smem_u32(smem);
    const uint32_t aHbase = base;
    const uint32_t aLbase = base + TILE_BYTES;
    const uint32_t bHbase = base + 2 * TILE_BYTES;
    const uint32_t bLbase = base + 3 * TILE_BYTES;

    const int arow    = R + (lane & 7) + ((lane >> 3) & 1) * 8;
    const int acolh   = (lane >> 4) * 8;
    const int brow_in = (lane & 7) + ((lane >= 16) ? 8 : 0);
    const int bcolh   = ((lane >> 3) & 1) * 8;

    #pragma unroll 1
    for (int kc = 0; kc < 8; kc++) {
        const int k0 = kc * 16;
        const uint32_t aoff = (uint32_t)((arow * SPAD + k0 + acolh) * 2);
        uint32_t ah0, ah1, ah2, ah3, al0, al1, al2, al3;
        LDSM4(ah0, ah1, ah2, ah3, aHbase + aoff);
        LDSM4(al0, al1, al2, al3, aLbase + aoff);

        #pragma unroll
        for (int np = 0; np < 4; np++) {
            const int ncol = C0 + np * 16;
            const uint32_t boff = (uint32_t)(((ncol + brow_in) * SPAD + k0 + bcolh) * 2);
            uint32_t bh0, bh1, bh2, bh3, bl0, bl1, bl2, bl3;
            LDSM4(bh0, bh1, bh2, bh3, bHbase + boff);
            LDSM4(bl0, bl1, bl2, bl3, bLbase + boff);
            MMA16816(acc[2 * np],     ah0, ah1, ah2, ah3, bh0, bh1);
            MMA16816(acc[2 * np + 1], ah0, ah1, ah2, ah3, bh2, bh3);
            MMA16816(acc[2 * np],     ah0, ah1, ah2, ah3, bl0, bl1);
            MMA16816(acc[2 * np + 1], ah0, ah1, ah2, ah3, bl2, bl3);
            MMA16816(acc[2 * np],     al0, al1, al2, al3, bh0, bh1);
            MMA16816(acc[2 * np + 1], al0, al1, al2, al3, bh2, bh3);
        }
    }

    // ---- Epilogue: accum regs -> g_support (float2, full 32B sectors) ----
    const int g   = lane >> 2;
    const int tig = lane & 3;
    const int m1  = m0 + R + g;
    const int m2  = m1 + 8;
    #pragma unroll
    for (int nt = 0; nt < 8; nt++) {
        const int c = C0 + nt * 8 + tig * 2;
        if (m1 < N_NODES)
            *(float2*)&g_support[(size_t)m1 * F + c] = make_float2(acc[nt][0], acc[nt][1]);
        if (m2 < N_NODES)
            *(float2*)&g_support[(size_t)m2 * F + c] = make_float2(acc[nt][2], acc[nt][3]);
    }
}

// ---------------------------------------------------------------------------
// Kernel 2: single-pass exclusive scan of g_count -> g_start
// 49 co-resident blocks; decoupled lookback, full-predecessor stride.
// ---------------------------------------------------------------------------
__global__ __launch_bounds__(1024) void scan_fused_kernel() {
    __shared__ int wsum[32];
    __shared__ int blk_prev;
    const int t    = threadIdx.x;
    const int bid  = blockIdx.x;
    const int lane = t & 31;
    const int wid  = t >> 5;
    const int idx  = bid * 1024 + t;

    const int v = (idx < N_NODES) ? g_count[idx] : 0;

    int s = v;
    #pragma unroll
    for (int off = 1; off < 32; off <<= 1) {
        int n = __shfl_up_sync(0xffffffffu, s, off);
        if (lane >= off) s += n;
    }
    if (lane == 31) wsum[wid] = s;
    __syncthreads();

    if (wid == 0) {
        int ws = wsum[lane];
        #pragma unroll
        for (int off = 1; off < 32; off <<= 1) {
            int n = __shfl_up_sync(0xffffffffu, ws, off);
            if (lane >= off) ws += n;
        }
        wsum[lane] = ws;
        if (lane == 31) atomicExch(&g_agg[bid], ws | AGG_FLAG);

        int a = 0;
        for (int p = lane; p < bid; p += 32) {
            volatile int* agg = g_agg;
            int xv;
            do { xv = agg[p]; } while (!(xv & AGG_FLAG));
            a += xv & (AGG_FLAG - 1);
        }
        #pragma unroll
        for (int off = 16; off >= 1; off >>= 1)
            a += __shfl_xor_sync(0xffffffffu, a, off);
        if (lane == 0) blk_prev = a;
    }
    __syncthreads();

    const int wexcl = (wid > 0) ? wsum[wid - 1] : 0;
    if (idx < N_NODES) g_start[idx] = blk_prev + wexcl + (s - v);
    if (idx == 0) g_start[N_NODES] = N_EDGES;
}

// ---------------------------------------------------------------------------
// Kernel 3: scatter edges into CSR order (atomicSub cursor -> back to 0)
// ---------------------------------------------------------------------------
__global__ void scatter_kernel(const int*   __restrict__ rows,
                               const int*   __restrict__ cols,
                               const float* __restrict__ vals) {
    int e = blockIdx.x * blockDim.x + threadIdx.x;
    if (e >= N_EDGES) return;
    int r = rows[e];
    int p = g_start[r] + atomicSub(&g_count[r], 1) - 1;
    g_edge[p] = make_int2(cols[e], __float_as_int(vals[e]));
}

// ---------------------------------------------------------------------------
// Kernel 4: CSR SpMM: warp per row, 4-edge ILP, atomic-free, bias fused
// ---------------------------------------------------------------------------
__global__ __launch_bounds__(256) void spmm_csr_kernel(const float* __restrict__ bias,
                                                       float*       __restrict__ out) {
    const int warp = (blockIdx.x * blockDim.x + threadIdx.x) >> 5;
    const int lane = threadIdx.x & 31;
    if (warp >= N_NODES) return;

    const int s = g_start[warp];
    const int e = g_start[warp + 1];

    float4 acc = ((const float4*)bias)[lane];

    int base = s;
    for (; base + 4 <= e; base += 4) {
        const int2 e0 = g_edge[base + 0];
        const int2 e1 = g_edge[base + 1];
        const int2 e2 = g_edge[base + 2];
        const int2 e3 = g_edge[base + 3];
        const float4 s0 = *(const float4*)&g_support[(size_t)e0.x * F + lane * 4];
        const float4 s1 = *(const float4*)&g_support[(size_t)e1.x * F + lane * 4];
        const float4 s2 = *(const float4*)&g_support[(size_t)e2.x * F + lane * 4];
        const float4 s3 = *(const float4*)&g_support[(size_t)e3.x * F + lane * 4];
        const float v0 = __int_as_float(e0.y);
        const float v1 = __int_as_float(e1.y);
        const float v2 = __int_as_float(e2.y);
        const float v3 = __int_as_float(e3.y);
        acc.x += v0 * s0.x; acc.y += v0 * s0.y; acc.z += v0 * s0.z; acc.w += v0 * s0.w;
        acc.x += v1 * s1.x; acc.y += v1 * s1.y; acc.z += v1 * s1.z; acc.w += v1 * s1.w;
        acc.x += v2 * s2.x; acc.y += v2 * s2.y; acc.z += v2 * s2.z; acc.w += v2 * s2.w;
        acc.x += v3 * s3.x; acc.y += v3 * s3.y; acc.z += v3 * s3.z; acc.w += v3 * s3.w;
    }
    for (; base < e; base++) {
        const int2  ed = g_edge[base];
        const float4 sv = *(const float4*)&g_support[(size_t)ed.x * F + lane * 4];
        const float  v  = __int_as_float(ed.y);
        acc.x += v * sv.x; acc.y += v * sv.y; acc.z += v * sv.z; acc.w += v * sv.w;
    }

    *(float4*)&out[(size_t)warp * F + lane * 4] = acc;
}

// ---------------------------------------------------------------------------
// Launch. Inputs: 0=x, 1=weight, 2=bias, 3=edge_vals, 4=edge_rows, 5=edge_cols
// ---------------------------------------------------------------------------
extern "C" void kernel_launch(void* const* d_in, const int* in_sizes, int n_in,
                              void* d_out, int out_size) {
    const float* x    = (const float*)d_in[0];
    const float* w    = (const float*)d_in[1];
    const float* bias = (const float*)d_in[2];
    const float* vals = (const float*)d_in[3];
    const int*   rows = (const int*)d_in[4];
    const int*   cols = (const int*)d_in[5];
    float*       out  = (float*)d_out;

    static bool attr_set = false;
    if (!attr_set) {
        cudaFuncSetAttribute(gemm_hist_kernel,
                             cudaFuncAttributeMaxDynamicSharedMemorySize, GEMM_SMEM);
        attr_set = true;
    }

    // 1) GEMM (support = x @ W) + fused histogram + flag reset
    gemm_hist_kernel<<<GEMM_BLOCKS, GEMM_THREADS, GEMM_SMEM>>>(x, w, rows);
    // 2) single-pass scan -> g_start
    scan_fused_kernel<<<SCAN_BLOCKS, 1024>>>();
    // 3) scatter into CSR order (cursor decrements back to 0)
    scatter_kernel<<<(N_EDGES + 255) / 256, 256>>>(rows, cols, vals);
    // 4) out = A_csr @ support + bias
    {
        const long long threads = (long long)N_NODES * 32;
        spmm_csr_kernel<<<(int)((threads + 255) / 256), 256>>>(bias, out);
    }
}